// round 9
// baseline (speedup 1.0000x reference)
#include <cuda_runtime.h>
#include <math.h>

// PSRoIPool (R-FCN), d-vectorized, ONE WARP per bin, one bin-row per block.
// R9 = R7 + rois staged into __constant__ memory (graph-legal D2D memcpy),
// cutting the ~250-600cyc global rois load off the head of every warp's
// dependency chain (LDC const-cache hit ~30cyc, uniform broadcast).
//
//   rois:     [N=128, 5]  (batch_idx, x1, y1, x2, y2)  float32
//   features: [B=2, C=392, H=50, W=84]                  float32
//   out:      [N, D=8, G=7, G=7]                        float32
//
// Grid (7, N): block (i, n) handles bin row i of roi n with 7 bins x 32
// lanes = 224 threads (7 warps/block, 896 blocks = 6272 warps -> ONE wave).
// Lanes tile the bin 8-wide (w) x 4-high (h); 8 w-lanes read a contiguous
// 32B sector per d-channel; 8 channel loads per pixel (MLP=8).

#define G   7
#define D   8
#define Hf  50
#define Wf  84
#define HW  (Hf * Wf)           // 4200
#define Cf  (D * G * G)         // 392
#define DSTRIDE (G * G * HW)    // 205800 floats between d-channels
#define NMAX 128

__constant__ float c_rois[NMAX * 5];

__global__ __launch_bounds__(G * 32) void psroi_warp_c_kernel(
    const float* __restrict__ feat,
    float* __restrict__ out,
    float scale)
{
    const int i = blockIdx.x;         // bin row 0..6
    const int n = blockIdx.y;         // roi
    const int t = threadIdx.x;        // 0..223

    const int lane = t & 31;
    const int j    = t >> 5;          // bin col 0..6 (one warp per bin)

    // ---- per-thread geometry from constant cache (uniform, ~30cyc) ----
    const float* r = c_rois + n * 5;
    const int   b  = (int)r[0];
    const float xs = rintf(r[1]) * scale;
    const float ys = rintf(r[2]) * scale;
    const float xe = (rintf(r[3]) + 1.0f) * scale;
    const float ye = (rintf(r[4]) + 1.0f) * scale;

    const float bw = fmaxf(xe - xs, 0.1f) * (1.0f / (float)G);
    const float bh = fmaxf(ye - ys, 0.1f) * (1.0f / (float)G);

    const int ws = (int)fminf(fmaxf(floorf((float)j * bw + xs), 0.0f), (float)Wf);
    const int we = (int)fminf(fmaxf(ceilf(((float)j + 1.0f) * bw + xs), 0.0f), (float)Wf);
    const int hs = (int)fminf(fmaxf(floorf((float)i * bh + ys), 0.0f), (float)Hf);
    const int he = (int)fminf(fmaxf(ceilf(((float)i + 1.0f) * bh + ys), 0.0f), (float)Hf);

    const int bwc = we - ws;          // >= 0 by construction
    const int bhc = he - hs;
    const float area = fmaxf((float)(bhc * bwc), 1.0f);

    const float* base = feat + ((size_t)b * Cf + i * G + j) * (size_t)HW;

    float acc[D];
    #pragma unroll
    for (int d = 0; d < D; ++d) acc[d] = 0.0f;

    // 2D-strided pixel loop: 8 lanes across w, 4 across h. No integer div.
    for (int hh = hs + (lane >> 3); hh < he; hh += 4) {
        const float* rowp = base + hh * Wf;
        for (int ww = ws + (lane & 7); ww < we; ww += 8) {
            #pragma unroll
            for (int d = 0; d < D; ++d)
                acc[d] += __ldg(rowp + ww + d * DSTRIDE);
        }
    }

    // ---- reduce-scatter butterfly over the full warp ----
    const unsigned gmask = 0xFFFFFFFFu;
    const int b0 = lane & 1, b1 = (lane >> 1) & 1, b2 = (lane >> 2) & 1;

    // level 1 (xor 1): keep d with bit0(d)==b0           -> 4 values
    float v1[4];
    #pragma unroll
    for (int k = 0; k < 4; ++k) {
        float keep = b0 ? acc[2 * k + 1] : acc[2 * k];
        float send = b0 ? acc[2 * k]     : acc[2 * k + 1];
        v1[k] = keep + __shfl_xor_sync(gmask, send, 1);
    }
    // level 2 (xor 2): keep k with bit0(k)==b1           -> 2 values
    float v2[2];
    #pragma unroll
    for (int m = 0; m < 2; ++m) {
        float keep = b1 ? v1[2 * m + 1] : v1[2 * m];
        float send = b1 ? v1[2 * m]     : v1[2 * m + 1];
        v2[m] = keep + __shfl_xor_sync(gmask, send, 2);
    }
    // level 3 (xor 4): keep m==b2                         -> 1 value, d = lane&7
    float v;
    {
        float keep = b2 ? v2[1] : v2[0];
        float send = b2 ? v2[0] : v2[1];
        v = keep + __shfl_xor_sync(gmask, send, 4);
    }
    // levels 4,5 (xor 8, xor 16): fold the four 8-lane replicas
    v += __shfl_xor_sync(gmask, v, 8);
    v += __shfl_xor_sync(gmask, v, 16);

    // lanes 0..7 write output d = lane:  out[n, d, i, j]
    if (lane < D)
        out[(size_t)n * Cf + lane * (G * G) + i * G + j] = __fdividef(v, area);
}

extern "C" void kernel_launch(void* const* d_in, const int* in_sizes, int n_in,
                              void* d_out, int out_size)
{
    const float* rois = (const float*)d_in[0];
    const float* feat = (const float*)d_in[1];
    (void)n_in; (void)out_size;

    const int stride = 16;                 // scalar input, constant for this problem
    const int N = in_sizes[0] / 5;         // 128
    float scale = 1.0f / (float)stride;

    // Stage rois into constant memory: device-to-device async copy is
    // graph-capturable (memcpy node) and allocation-free.
    cudaMemcpyToSymbolAsync(c_rois, rois, (size_t)(N * 5) * sizeof(float),
                            0, cudaMemcpyDeviceToDevice, 0);

    dim3 grid(G, N);                       // (7, 128) = 896 blocks
    psroi_warp_c_kernel<<<grid, G * 32>>>(feat, (float*)d_out, scale);
}

// round 10
// speedup vs baseline: 1.2237x; 1.2237x over previous
#include <cuda_runtime.h>
#include <math.h>

// PSRoIPool (R-FCN), d-vectorized, ONE WARP per bin, one bin-row per block.
// R10 = R7 (best: 6.62us) + h-loop unrolled x2 (predicated second body):
// issues the hh and hh+4 pixel loads together (8 -> 16 loads in flight),
// halving the exposed L2-latency rounds for the slowest (largest-roi) warps.
// Single kernel node, single wave (896 blocks x 7 warps = 6272 warps).
//
//   rois:     [N=128, 5]  (batch_idx, x1, y1, x2, y2)  float32
//   features: [B=2, C=392, H=50, W=84]                  float32
//   out:      [N, D=8, G=7, G=7]                        float32

#define G   7
#define D   8
#define Hf  50
#define Wf  84
#define HW  (Hf * Wf)           // 4200
#define Cf  (D * G * G)         // 392
#define DSTRIDE (G * G * HW)    // 205800 floats between d-channels

__global__ __launch_bounds__(G * 32) void psroi_warp_u2_kernel(
    const float* __restrict__ rois,
    const float* __restrict__ feat,
    float* __restrict__ out,
    float scale)
{
    const int i = blockIdx.x;         // bin row 0..6
    const int n = blockIdx.y;         // roi
    const int t = threadIdx.x;        // 0..223

    const int lane = t & 31;
    const int j    = t >> 5;          // bin col 0..6 (one warp per bin)

    // ---- per-thread geometry (warp-uniform rois load, L1-resident) ----
    const float* r = rois + n * 5;
    const int   b  = (int)__ldg(r + 0);
    const float xs = rintf(__ldg(r + 1)) * scale;
    const float ys = rintf(__ldg(r + 2)) * scale;
    const float xe = (rintf(__ldg(r + 3)) + 1.0f) * scale;
    const float ye = (rintf(__ldg(r + 4)) + 1.0f) * scale;

    const float bw = fmaxf(xe - xs, 0.1f) * (1.0f / (float)G);
    const float bh = fmaxf(ye - ys, 0.1f) * (1.0f / (float)G);

    const int ws = (int)fminf(fmaxf(floorf((float)j * bw + xs), 0.0f), (float)Wf);
    const int we = (int)fminf(fmaxf(ceilf(((float)j + 1.0f) * bw + xs), 0.0f), (float)Wf);
    const int hs = (int)fminf(fmaxf(floorf((float)i * bh + ys), 0.0f), (float)Hf);
    const int he = (int)fminf(fmaxf(ceilf(((float)i + 1.0f) * bh + ys), 0.0f), (float)Hf);

    const int bwc = we - ws;          // >= 0 by construction
    const int bhc = he - hs;
    const float area = fmaxf((float)(bhc * bwc), 1.0f);

    const float* base = feat + ((size_t)b * Cf + i * G + j) * (size_t)HW;

    float acc[D];
    #pragma unroll
    for (int d = 0; d < D; ++d) acc[d] = 0.0f;

    // Pixel loop: 8 lanes across w, 4 across h, h unrolled x2 (stride 8,
    // predicated +4 body) so both rows' loads issue before the FADD chain.
    for (int hh = hs + (lane >> 3); hh < he; hh += 8) {
        const float* rowp  = base + hh * Wf;
        const bool   have2 = (hh + 4) < he;
        for (int ww = ws + (lane & 7); ww < we; ww += 8) {
            float v0[D], v1[D];
            #pragma unroll
            for (int d = 0; d < D; ++d)
                v0[d] = __ldg(rowp + ww + d * DSTRIDE);
            if (have2) {
                #pragma unroll
                for (int d = 0; d < D; ++d)
                    v1[d] = __ldg(rowp + 4 * Wf + ww + d * DSTRIDE);
                #pragma unroll
                for (int d = 0; d < D; ++d)
                    acc[d] += v0[d] + v1[d];
            } else {
                #pragma unroll
                for (int d = 0; d < D; ++d)
                    acc[d] += v0[d];
            }
        }
    }

    // ---- reduce-scatter butterfly over the full warp ----
    const unsigned gmask = 0xFFFFFFFFu;
    const int b0 = lane & 1, b1 = (lane >> 1) & 1, b2 = (lane >> 2) & 1;

    // level 1 (xor 1): keep d with bit0(d)==b0           -> 4 values
    float v1r[4];
    #pragma unroll
    for (int k = 0; k < 4; ++k) {
        float keep = b0 ? acc[2 * k + 1] : acc[2 * k];
        float send = b0 ? acc[2 * k]     : acc[2 * k + 1];
        v1r[k] = keep + __shfl_xor_sync(gmask, send, 1);
    }
    // level 2 (xor 2): keep k with bit0(k)==b1           -> 2 values
    float v2r[2];
    #pragma unroll
    for (int m = 0; m < 2; ++m) {
        float keep = b1 ? v1r[2 * m + 1] : v1r[2 * m];
        float send = b1 ? v1r[2 * m]     : v1r[2 * m + 1];
        v2r[m] = keep + __shfl_xor_sync(gmask, send, 2);
    }
    // level 3 (xor 4): keep m==b2                         -> 1 value, d = lane&7
    float v;
    {
        float keep = b2 ? v2r[1] : v2r[0];
        float send = b2 ? v2r[0] : v2r[1];
        v = keep + __shfl_xor_sync(gmask, send, 4);
    }
    // levels 4,5 (xor 8, xor 16): fold the four 8-lane replicas
    v += __shfl_xor_sync(gmask, v, 8);
    v += __shfl_xor_sync(gmask, v, 16);

    // lanes 0..7 write output d = lane:  out[n, d, i, j]
    if (lane < D)
        out[(size_t)n * Cf + lane * (G * G) + i * G + j] = __fdividef(v, area);
}

extern "C" void kernel_launch(void* const* d_in, const int* in_sizes, int n_in,
                              void* d_out, int out_size)
{
    const float* rois = (const float*)d_in[0];
    const float* feat = (const float*)d_in[1];
    (void)n_in; (void)out_size;

    const int stride = 16;                 // scalar input, constant for this problem
    const int N = in_sizes[0] / 5;         // 128
    float scale = 1.0f / (float)stride;

    dim3 grid(G, N);                       // (7, 128) = 896 blocks, single node
    psroi_warp_u2_kernel<<<grid, G * 32>>>(rois, feat, (float*)d_out, scale);
}

// round 12
// speedup vs baseline: 1.3413x; 1.0962x over previous
#include <cuda_runtime.h>
#include <math.h>

// PSRoIPool (R-FCN), d-vectorized, ONE WARP per bin, one bin-row per block.
// R11 = R7 (best: 6.62us) with instruction trims: 32-bit indexing (feat is
// 13.2MB, all offsets fit int), folded channel/output offset math. Structure
// unchanged: single kernel node, single wave (896 blocks x 7 warps).
//
//   rois:     [N=128, 5]  (batch_idx, x1, y1, x2, y2)  float32
//   features: [B=2, C=392, H=50, W=84]                  float32
//   out:      [N, D=8, G=7, G=7]                        float32

#define G   7
#define D   8
#define Hf  50
#define Wf  84
#define HW  (Hf * Wf)           // 4200
#define Cf  (D * G * G)         // 392
#define DSTRIDE (G * G * HW)    // 205800 floats between d-channels

__global__ __launch_bounds__(G * 32) void psroi_warp_i32_kernel(
    const float* __restrict__ rois,
    const float* __restrict__ feat,
    float* __restrict__ out,
    float scale)
{
    const int i = blockIdx.x;         // bin row 0..6
    const int n = blockIdx.y;         // roi
    const int t = threadIdx.x;        // 0..223

    const int lane = t & 31;
    const int j    = t >> 5;          // bin col 0..6 (one warp per bin)
    const int ij   = i * G + j;       // channel block offset

    // ---- per-thread geometry (warp-uniform rois load, L1-resident) ----
    const float* r = rois + n * 5;
    const int   b  = (int)__ldg(r + 0);
    const float xs = rintf(__ldg(r + 1)) * scale;
    const float ys = rintf(__ldg(r + 2)) * scale;
    const float xe = (rintf(__ldg(r + 3)) + 1.0f) * scale;
    const float ye = (rintf(__ldg(r + 4)) + 1.0f) * scale;

    const float bw = fmaxf(xe - xs, 0.1f) * (1.0f / (float)G);
    const float bh = fmaxf(ye - ys, 0.1f) * (1.0f / (float)G);

    const int ws = (int)fminf(fmaxf(floorf((float)j * bw + xs), 0.0f), (float)Wf);
    const int we = (int)fminf(fmaxf(ceilf(((float)j + 1.0f) * bw + xs), 0.0f), (float)Wf);
    const int hs = (int)fminf(fmaxf(floorf((float)i * bh + ys), 0.0f), (float)Hf);
    const int he = (int)fminf(fmaxf(ceilf(((float)i + 1.0f) * bh + ys), 0.0f), (float)Hf);

    const float area = fmaxf((float)((he - hs) * (we - ws)), 1.0f);

    // 32-bit base offset: b*Cf*HW + ij*HW  (max ~3.3M floats, fits easily)
    const float* base = feat + (b * Cf + ij) * HW;

    float acc[D];
    #pragma unroll
    for (int d = 0; d < D; ++d) acc[d] = 0.0f;

    // 2D-strided pixel loop: 8 lanes across w, 4 across h. No integer div.
    const int h0 = hs + (lane >> 3);
    const int w0 = ws + (lane & 7);
    for (int hh = h0; hh < he; hh += 4) {
        const float* rowp = base + hh * Wf;
        for (int ww = w0; ww < we; ww += 8) {
            #pragma unroll
            for (int d = 0; d < D; ++d)
                acc[d] += __ldg(rowp + ww + d * DSTRIDE);
        }
    }

    // ---- reduce-scatter butterfly over the full warp ----
    const unsigned gmask = 0xFFFFFFFFu;
    const int b0 = lane & 1, b1 = (lane >> 1) & 1, b2 = (lane >> 2) & 1;

    // level 1 (xor 1): keep d with bit0(d)==b0           -> 4 values
    float v1[4];
    #pragma unroll
    for (int k = 0; k < 4; ++k) {
        float keep = b0 ? acc[2 * k + 1] : acc[2 * k];
        float send = b0 ? acc[2 * k]     : acc[2 * k + 1];
        v1[k] = keep + __shfl_xor_sync(gmask, send, 1);
    }
    // level 2 (xor 2): keep k with bit0(k)==b1           -> 2 values
    float v2[2];
    #pragma unroll
    for (int m = 0; m < 2; ++m) {
        float keep = b1 ? v1[2 * m + 1] : v1[2 * m];
        float send = b1 ? v1[2 * m]     : v1[2 * m + 1];
        v2[m] = keep + __shfl_xor_sync(gmask, send, 2);
    }
    // level 3 (xor 4): keep m==b2                         -> 1 value, d = lane&7
    float v;
    {
        float keep = b2 ? v2[1] : v2[0];
        float send = b2 ? v2[0] : v2[1];
        v = keep + __shfl_xor_sync(gmask, send, 4);
    }
    // levels 4,5 (xor 8, xor 16): fold the four 8-lane replicas
    v += __shfl_xor_sync(gmask, v, 8);
    v += __shfl_xor_sync(gmask, v, 16);

    // lanes 0..7 write output d = lane:  out[n*Cf + d*49 + ij]
    if (lane < D)
        out[n * Cf + lane * (G * G) + ij] = __fdividef(v, area);
}

extern "C" void kernel_launch(void* const* d_in, const int* in_sizes, int n_in,
                              void* d_out, int out_size)
{
    const float* rois = (const float*)d_in[0];
    const float* feat = (const float*)d_in[1];
    (void)n_in; (void)out_size;

    const int stride = 16;                 // scalar input, constant for this problem
    const int N = in_sizes[0] / 5;         // 128
    float scale = 1.0f / (float)stride;

    dim3 grid(G, N);                       // (7, 128) = 896 blocks, single node
    psroi_warp_i32_kernel<<<grid, G * 32>>>(rois, feat, (float*)d_out, scale);
}

// round 14
// speedup vs baseline: 1.3478x; 1.0048x over previous
#include <cuda_runtime.h>
#include <math.h>

// PSRoIPool (R-FCN), d-vectorized, ONE WARP per bin, one bin-row per block.
// R13 = R11 with strength-reduced loop control: running row/pixel pointers
// (no per-iteration IMAD address rebuild; d-offsets are LDG immediates),
// count-based loop exits. Structure unchanged from the 6.62us R7 optimum:
// single kernel node, single wave (896 blocks x 7 warps = 6272 warps).
//
//   rois:     [N=128, 5]  (batch_idx, x1, y1, x2, y2)  float32
//   features: [B=2, C=392, H=50, W=84]                  float32
//   out:      [N, D=8, G=7, G=7]                        float32

#define G   7
#define D   8
#define Hf  50
#define Wf  84
#define HW  (Hf * Wf)           // 4200
#define Cf  (D * G * G)         // 392
#define DSTRIDE (G * G * HW)    // 205800 floats between d-channels (823200 B < 8MB imm)

__global__ __launch_bounds__(G * 32) void psroi_warp_sr_kernel(
    const float* __restrict__ rois,
    const float* __restrict__ feat,
    float* __restrict__ out,
    float scale)
{
    const int i = blockIdx.x;         // bin row 0..6
    const int n = blockIdx.y;         // roi
    const int t = threadIdx.x;        // 0..223

    const int lane = t & 31;
    const int j    = t >> 5;          // bin col 0..6 (one warp per bin)
    const int ij   = i * G + j;       // channel block offset

    // ---- per-thread geometry (warp-uniform rois load, L1-resident) ----
    const float* r = rois + n * 5;
    const int   b  = (int)__ldg(r + 0);
    const float xs = rintf(__ldg(r + 1)) * scale;
    const float ys = rintf(__ldg(r + 2)) * scale;
    const float xe = (rintf(__ldg(r + 3)) + 1.0f) * scale;
    const float ye = (rintf(__ldg(r + 4)) + 1.0f) * scale;

    const float bw = fmaxf(xe - xs, 0.1f) * (1.0f / (float)G);
    const float bh = fmaxf(ye - ys, 0.1f) * (1.0f / (float)G);

    const int ws = (int)fminf(fmaxf(floorf((float)j * bw + xs), 0.0f), (float)Wf);
    const int we = (int)fminf(fmaxf(ceilf(((float)j + 1.0f) * bw + xs), 0.0f), (float)Wf);
    const int hs = (int)fminf(fmaxf(floorf((float)i * bh + ys), 0.0f), (float)Hf);
    const int he = (int)fminf(fmaxf(ceilf(((float)i + 1.0f) * bh + ys), 0.0f), (float)Hf);

    const float area = fmaxf((float)((he - hs) * (we - ws)), 1.0f);

    // This lane's tile position: 8 lanes across w, 4 across h.
    const int h0 = hs + (lane >> 3);
    const int w0 = ws + (lane & 7);
    // Iteration counts (ceil-div of remaining extent; <=0 means no work).
    const int nh = (he - h0 + 3) >> 2;      // rows this lane visits (stride 4)
    const int nw = (we - w0 + 7) >> 3;      // cols this lane visits (stride 8)

    float acc[D];
    #pragma unroll
    for (int d = 0; d < D; ++d) acc[d] = 0.0f;

    if (nh > 0 && nw > 0) {
        const float* rowp = feat + (b * Cf + ij) * HW + h0 * Wf + w0;
        for (int hc = nh; hc > 0; --hc, rowp += 4 * Wf) {
            const float* px = rowp;
            for (int wc = nw; wc > 0; --wc, px += 8) {
                #pragma unroll
                for (int d = 0; d < D; ++d)
                    acc[d] += __ldg(px + d * DSTRIDE);   // LDG [R+imm]
            }
        }
    }

    // ---- reduce-scatter butterfly over the full warp ----
    const unsigned gmask = 0xFFFFFFFFu;
    const int b0 = lane & 1, b1 = (lane >> 1) & 1, b2 = (lane >> 2) & 1;

    // level 1 (xor 1): keep d with bit0(d)==b0           -> 4 values
    float v1[4];
    #pragma unroll
    for (int k = 0; k < 4; ++k) {
        float keep = b0 ? acc[2 * k + 1] : acc[2 * k];
        float send = b0 ? acc[2 * k]     : acc[2 * k + 1];
        v1[k] = keep + __shfl_xor_sync(gmask, send, 1);
    }
    // level 2 (xor 2): keep k with bit0(k)==b1           -> 2 values
    float v2[2];
    #pragma unroll
    for (int m = 0; m < 2; ++m) {
        float keep = b1 ? v1[2 * m + 1] : v1[2 * m];
        float send = b1 ? v1[2 * m]     : v1[2 * m + 1];
        v2[m] = keep + __shfl_xor_sync(gmask, send, 2);
    }
    // level 3 (xor 4): keep m==b2                         -> 1 value, d = lane&7
    float v;
    {
        float keep = b2 ? v2[1] : v2[0];
        float send = b2 ? v2[0] : v2[1];
        v = keep + __shfl_xor_sync(gmask, send, 4);
    }
    // levels 4,5 (xor 8, xor 16): fold the four 8-lane replicas
    v += __shfl_xor_sync(gmask, v, 8);
    v += __shfl_xor_sync(gmask, v, 16);

    // lanes 0..7 write output d = lane:  out[n*Cf + d*49 + ij]
    if (lane < D)
        out[n * Cf + lane * (G * G) + ij] = __fdividef(v, area);
}

extern "C" void kernel_launch(void* const* d_in, const int* in_sizes, int n_in,
                              void* d_out, int out_size)
{
    const float* rois = (const float*)d_in[0];
    const float* feat = (const float*)d_in[1];
    (void)n_in; (void)out_size;

    const int stride = 16;                 // scalar input, constant for this problem
    const int N = in_sizes[0] / 5;         // 128
    float scale = 1.0f / (float)stride;

    dim3 grid(G, N);                       // (7, 128) = 896 blocks, single node
    psroi_warp_sr_kernel<<<grid, G * 32>>>(rois, feat, (float*)d_out, scale);
}